// round 1
// baseline (speedup 1.0000x reference)
#include <cuda_runtime.h>
#include <math.h>
#include <stdint.h>

// ---------------- problem constants ----------------
#define NTOK   4096            // B*S
#define HIDDIM 2048
#define QLR    1536
#define KVLR   512
#define HEADS  16
#define NOPE   128
#define ROPED  64
#define HD     192             // NOPE+ROPE
#define VDIM   128
#define SEQ    1024
#define BATCH  4
#define QDIM   (HEADS*HD)      // 3072
#define KVDIM  (KVLR+ROPED)    // 576
#define KNOPE_DIM (HEADS*NOPE) // 2048
#define VVDIM  (HEADS*VDIM)    // 2048

// ---------------- device scratch (allowed: __device__ globals) ----------------
__device__ float g_qa   [(size_t)NTOK*QLR];
__device__ float g_q    [(size_t)NTOK*QDIM];
__device__ float g_kv   [(size_t)NTOK*KVDIM];
__device__ float g_ckv  [(size_t)NTOK*KVLR];
__device__ float g_kpe  [(size_t)NTOK*ROPED];
__device__ float g_knope[(size_t)NTOK*KNOPE_DIM];
__device__ float g_v    [(size_t)NTOK*VVDIM];
__device__ float g_ao   [(size_t)NTOK*VVDIM];

// ---------------- block reduce ----------------
__device__ __forceinline__ float block_sum256(float v) {
    __shared__ float red[8];
    int lane = threadIdx.x & 31, w = threadIdx.x >> 5;
    #pragma unroll
    for (int o = 16; o; o >>= 1) v += __shfl_xor_sync(0xffffffffu, v, o);
    if (lane == 0) red[w] = v;
    __syncthreads();
    if (threadIdx.x == 0) {
        float t = 0.f;
        #pragma unroll
        for (int i = 0; i < 8; i++) t += red[i];
        red[0] = t;
    }
    __syncthreads();
    return red[0];
}

// ---------------- SGEMM: C[M,N] = A[M,K] * B[N,K]^T ----------------
// 128x128 tile, BK=16, 256 threads, 8x8 per thread. M%128==0, K%16==0. N guarded.
__global__ __launch_bounds__(256) void sgemm_tn(
    const float* __restrict__ A, const float* __restrict__ B, float* __restrict__ C,
    int M, int N, int K)
{
    __shared__ float As[16][128];
    __shared__ float Bs[16][128];
    const int bm = blockIdx.y * 128;
    const int bn = blockIdx.x * 128;
    const int tid = threadIdx.x;
    const int tx = tid & 15, ty = tid >> 4;

    float acc[8][8];
    #pragma unroll
    for (int i = 0; i < 8; i++)
        #pragma unroll
        for (int j = 0; j < 8; j++) acc[i][j] = 0.f;

    const int lr = tid >> 2;          // 0..63
    const int lc = (tid & 3) * 4;     // 0,4,8,12

    for (int k0 = 0; k0 < K; k0 += 16) {
        #pragma unroll
        for (int h = 0; h < 2; h++) {
            int r = lr + h * 64;
            float4 va = *(const float4*)(A + (size_t)(bm + r) * K + k0 + lc);
            As[lc + 0][r] = va.x; As[lc + 1][r] = va.y;
            As[lc + 2][r] = va.z; As[lc + 3][r] = va.w;
            int gn = bn + r;
            float4 vb = make_float4(0.f, 0.f, 0.f, 0.f);
            if (gn < N) vb = *(const float4*)(B + (size_t)gn * K + k0 + lc);
            Bs[lc + 0][r] = vb.x; Bs[lc + 1][r] = vb.y;
            Bs[lc + 2][r] = vb.z; Bs[lc + 3][r] = vb.w;
        }
        __syncthreads();
        #pragma unroll
        for (int kk = 0; kk < 16; kk++) {
            float a[8], b[8];
            *(float4*)&a[0] = *(float4*)&As[kk][ty * 4];
            *(float4*)&a[4] = *(float4*)&As[kk][64 + ty * 4];
            *(float4*)&b[0] = *(float4*)&Bs[kk][tx * 4];
            *(float4*)&b[4] = *(float4*)&Bs[kk][64 + tx * 4];
            #pragma unroll
            for (int i = 0; i < 8; i++)
                #pragma unroll
                for (int j = 0; j < 8; j++)
                    acc[i][j] = fmaf(a[i], b[j], acc[i][j]);
        }
        __syncthreads();
    }

    #pragma unroll
    for (int i = 0; i < 8; i++) {
        int row = bm + ((i < 4) ? (ty * 4 + i) : (64 + ty * 4 + i - 4));
        #pragma unroll
        for (int jh = 0; jh < 2; jh++) {
            int col = bn + tx * 4 + jh * 64;
            if (col < N) {
                float4 v = make_float4(acc[i][jh * 4 + 0], acc[i][jh * 4 + 1],
                                       acc[i][jh * 4 + 2], acc[i][jh * 4 + 3]);
                *(float4*)(C + (size_t)row * N + col) = v;
            }
        }
    }
}

// ---------------- rmsnorm (full row) ----------------
__global__ void rmsnorm_k(const float* __restrict__ in, const float* __restrict__ w,
                          float* __restrict__ out, int len)
{
    int row = blockIdx.x;
    const float* h = in + (size_t)row * len;
    float ss = 0.f;
    for (int i = threadIdx.x; i < len; i += blockDim.x) { float v = h[i]; ss += v * v; }
    ss = block_sum256(ss);
    float sc = rsqrtf(ss / (float)len + 1e-6f);
    float* o = out + (size_t)row * len;
    for (int i = threadIdx.x; i < len; i += blockDim.x) o[i] = h[i] * sc * w[i];
}

// ---------------- kv split: rmsnorm first 512 -> ckv ; rope last 64 -> kpe ----------------
__global__ void kv_norm_rope_k(const float* __restrict__ w,
                               const float* __restrict__ sin_t,
                               const float* __restrict__ cos_t)
{
    int row = blockIdx.x;
    const float* h = g_kv + (size_t)row * KVDIM;
    float ss = 0.f;
    for (int i = threadIdx.x; i < KVLR; i += blockDim.x) { float v = h[i]; ss += v * v; }
    ss = block_sum256(ss);
    float sc = rsqrtf(ss / (float)KVLR + 1e-6f);
    for (int i = threadIdx.x; i < KVLR; i += blockDim.x)
        g_ckv[(size_t)row * KVLR + i] = h[i] * sc * w[i];
    if (threadIdx.x < ROPED / 2) {
        int i = threadIdx.x;
        int pos = row & (SEQ - 1);
        float s = sin_t[pos * 32 + i], c = cos_t[pos * 32 + i];
        float e = h[KVLR + 2 * i], o = h[KVLR + 2 * i + 1];
        g_kpe[(size_t)row * ROPED + 2 * i]     = e * c - o * s;
        g_kpe[(size_t)row * ROPED + 2 * i + 1] = e * s + o * c;
    }
}

// ---------------- rope on q_pe (in place on g_q) ----------------
__global__ void q_rope_k(const float* __restrict__ sin_t, const float* __restrict__ cos_t)
{
    int idx = blockIdx.x * blockDim.x + threadIdx.x;
    if (idx >= NTOK * HEADS * (ROPED / 2)) return;
    int i   = idx & 31;
    int hh  = (idx >> 5) & 15;
    int row = idx >> 9;
    int pos = row & (SEQ - 1);
    float* p = g_q + (size_t)row * QDIM + hh * HD + NOPE + 2 * i;
    float s = sin_t[pos * 32 + i], c = cos_t[pos * 32 + i];
    float e = p[0], o = p[1];
    p[0] = e * c - o * s;
    p[1] = e * s + o * c;
}

// ---------------- flash attention (causal, fp32) ----------------
// grid (SEQ/64, HEADS, BATCH), 256 threads, dynamic smem.
#define AT_THREADS 256
#define QKSTR 196      // 192 + 4 pad: conflict-free K row reads
#define PSTR  65

__global__ __launch_bounds__(AT_THREADS) void attn_k()
{
    extern __shared__ float sm[];
    float* Qs   = sm;                         // 64 x QKSTR
    float* Ks   = Qs + 64 * QKSTR;            // 64 x QKSTR
    float* Vs   = Ks + 64 * QKSTR;            // 64 x 128
    float* Ps   = Vs + 64 * VDIM;             // 64 x PSTR
    float* mrow = Ps + 64 * PSTR;
    float* lrow = mrow + 64;
    float* arow = lrow + 64;

    const int qt = blockIdx.x, hh = blockIdx.y, b = blockIdx.z;
    const int tid = threadIdx.x;
    const int q0 = qt * 64;                   // seq-local
    const int grow0 = b * SEQ + q0;

    // load Q tile (64 x 192)
    for (int t = tid; t < 64 * 48; t += AT_THREADS) {
        int r = t / 48, c = t % 48;
        float4 v = *(const float4*)(g_q + (size_t)(grow0 + r) * QDIM + hh * HD + c * 4);
        *(float4*)&Qs[r * QKSTR + c * 4] = v;
    }
    if (tid < 64) { mrow[tid] = -INFINITY; lrow[tid] = 0.f; }

    float4 O4[8];
    #pragma unroll
    for (int k = 0; k < 8; k++) O4[k] = make_float4(0.f, 0.f, 0.f, 0.f);

    const int tx = tid & 15, ty = tid >> 4;   // S-compute mapping
    const int pr = tid >> 2;                  // PV row (0..63)
    const int cb = (tid & 3) * 4;             // PV col base

    __syncthreads();

    const float scale = 0.07216878364870323f; // 1/sqrt(192)

    for (int kt = 0; kt <= qt; kt++) {
        const int k0 = kt * 64;
        const int gk0 = b * SEQ + k0;

        // load K (nope|pe) and V tiles
        for (int t = tid; t < 64 * 48; t += AT_THREADS) {
            int r = t / 48, c = t % 48;
            float4 v;
            if (c < 32)
                v = *(const float4*)(g_knope + (size_t)(gk0 + r) * KNOPE_DIM + hh * NOPE + c * 4);
            else
                v = *(const float4*)(g_kpe + (size_t)(gk0 + r) * ROPED + (c - 32) * 4);
            *(float4*)&Ks[r * QKSTR + c * 4] = v;
        }
        for (int t = tid; t < 64 * 32; t += AT_THREADS) {
            int r = t / 32, c = t % 32;
            *(float4*)&Vs[r * VDIM + c * 4] =
                *(const float4*)(g_v + (size_t)(gk0 + r) * VVDIM + hh * VDIM + c * 4);
        }
        __syncthreads();

        // S = Q K^T (rows ty*4+ii, cols tx+16*jj)
        float sacc[4][4] = {};
        #pragma unroll 4
        for (int d = 0; d < HD; d += 4) {
            float4 qv[4], kv4[4];
            #pragma unroll
            for (int ii = 0; ii < 4; ii++) qv[ii]  = *(float4*)&Qs[(ty * 4 + ii) * QKSTR + d];
            #pragma unroll
            for (int jj = 0; jj < 4; jj++) kv4[jj] = *(float4*)&Ks[(tx + 16 * jj) * QKSTR + d];
            #pragma unroll
            for (int ii = 0; ii < 4; ii++)
                #pragma unroll
                for (int jj = 0; jj < 4; jj++)
                    sacc[ii][jj] += qv[ii].x * kv4[jj].x + qv[ii].y * kv4[jj].y
                                  + qv[ii].z * kv4[jj].z + qv[ii].w * kv4[jj].w;
        }
        #pragma unroll
        for (int ii = 0; ii < 4; ii++)
            #pragma unroll
            for (int jj = 0; jj < 4; jj++) {
                int qi = q0 + ty * 4 + ii;
                int kj = k0 + tx + 16 * jj;
                Ps[(ty * 4 + ii) * PSTR + tx + 16 * jj] =
                    (kj <= qi) ? sacc[ii][jj] * scale : -1e30f;
            }
        __syncthreads();

        // online softmax: 8 warps x 8 rows
        {
            int lane = tid & 31;
            int rbase = (tid >> 5) * 8;
            #pragma unroll
            for (int rr = 0; rr < 8; rr++) {
                int r = rbase + rr;
                float v0 = Ps[r * PSTR + lane];
                float v1 = Ps[r * PSTR + 32 + lane];
                float mx = fmaxf(v0, v1);
                #pragma unroll
                for (int o = 16; o; o >>= 1) mx = fmaxf(mx, __shfl_xor_sync(0xffffffffu, mx, o));
                float mold = mrow[r];
                float mnew = fmaxf(mold, mx);
                float p0 = __expf(v0 - mnew), p1 = __expf(v1 - mnew);
                Ps[r * PSTR + lane] = p0;
                Ps[r * PSTR + 32 + lane] = p1;
                float s = p0 + p1;
                #pragma unroll
                for (int o = 16; o; o >>= 1) s += __shfl_xor_sync(0xffffffffu, s, o);
                if (lane == 0) {
                    float a = (mold > -1e30f) ? __expf(mold - mnew) : 0.f;
                    arow[r] = a;
                    lrow[r] = lrow[r] * a + s;
                    mrow[r] = mnew;
                }
            }
        }
        __syncthreads();

        // rescale O, accumulate P @ V
        {
            float a = arow[pr];
            #pragma unroll
            for (int k = 0; k < 8; k++) {
                O4[k].x *= a; O4[k].y *= a; O4[k].z *= a; O4[k].w *= a;
            }
            #pragma unroll 2
            for (int j = 0; j < 64; j++) {
                float p = Ps[pr * PSTR + j];
                #pragma unroll
                for (int k = 0; k < 8; k++) {
                    float4 v = *(float4*)&Vs[j * VDIM + cb + 16 * k];
                    O4[k].x = fmaf(p, v.x, O4[k].x);
                    O4[k].y = fmaf(p, v.y, O4[k].y);
                    O4[k].z = fmaf(p, v.z, O4[k].z);
                    O4[k].w = fmaf(p, v.w, O4[k].w);
                }
            }
        }
        __syncthreads();   // protect Ks/Vs/Ps for next tile
    }

    float inv = 1.f / lrow[pr];
    #pragma unroll
    for (int k = 0; k < 8; k++) {
        float4 v = make_float4(O4[k].x * inv, O4[k].y * inv, O4[k].z * inv, O4[k].w * inv);
        *(float4*)(g_ao + (size_t)(grow0 + pr) * VVDIM + hh * VDIM + cb + 16 * k) = v;
    }
}

// ---------------- host launch ----------------
extern "C" void kernel_launch(void* const* d_in, const int* in_sizes, int n_in,
                              void* d_out, int out_size)
{
    const float* x        = (const float*)d_in[0];
    const float* wq_a     = (const float*)d_in[1];
    const float* w_qa_ln  = (const float*)d_in[2];
    const float* wq_b     = (const float*)d_in[3];
    const float* wkv_a    = (const float*)d_in[4];
    const float* w_kva_ln = (const float*)d_in[5];
    const float* wk_b     = (const float*)d_in[6];
    const float* wv_b     = (const float*)d_in[7];
    const float* wo       = (const float*)d_in[8];
    const float* rsin     = (const float*)d_in[9];
    const float* rcos     = (const float*)d_in[10];
    float* out = (float*)d_out;

    float *qa, *q, *kv, *ckv, *knope, *v, *ao;
    cudaGetSymbolAddress((void**)&qa,    g_qa);
    cudaGetSymbolAddress((void**)&q,     g_q);
    cudaGetSymbolAddress((void**)&kv,    g_kv);
    cudaGetSymbolAddress((void**)&ckv,   g_ckv);
    cudaGetSymbolAddress((void**)&knope, g_knope);
    cudaGetSymbolAddress((void**)&v,     g_v);
    cudaGetSymbolAddress((void**)&ao,    g_ao);

    // q_a = x @ wq_a^T ; rmsnorm ; q = q_a @ wq_b^T
    sgemm_tn<<<dim3(QLR / 128, NTOK / 128), 256>>>(x, wq_a, qa, NTOK, QLR, HIDDIM);
    rmsnorm_k<<<NTOK, 256>>>(qa, w_qa_ln, qa, QLR);
    sgemm_tn<<<dim3(QDIM / 128, NTOK / 128), 256>>>(qa, wq_b, q, NTOK, QDIM, QLR);

    // kv = x @ wkv_a^T ; split norm + k_pe rope
    sgemm_tn<<<dim3((KVDIM + 127) / 128, NTOK / 128), 256>>>(x, wkv_a, kv, NTOK, KVDIM, HIDDIM);
    kv_norm_rope_k<<<NTOK, 256>>>(w_kva_ln, rsin, rcos);

    // k_nope = ckv @ wk_b^T ; v = ckv @ wv_b^T
    sgemm_tn<<<dim3(KNOPE_DIM / 128, NTOK / 128), 256>>>(ckv, wk_b, knope, NTOK, KNOPE_DIM, KVLR);
    sgemm_tn<<<dim3(VVDIM / 128, NTOK / 128), 256>>>(ckv, wv_b, v, NTOK, VVDIM, KVLR);

    // rope on q_pe
    q_rope_k<<<(NTOK * HEADS * 32 + 255) / 256, 256>>>(rsin, rcos);

    // attention
    size_t shm = (size_t)(2 * 64 * QKSTR + 64 * VDIM + 64 * PSTR + 192) * sizeof(float);
    cudaFuncSetAttribute(attn_k, cudaFuncAttributeMaxDynamicSharedMemorySize, (int)shm);
    attn_k<<<dim3(SEQ / 64, HEADS, BATCH), AT_THREADS, shm>>>();

    // out = ao @ wo^T
    sgemm_tn<<<dim3(HIDDIM / 128, NTOK / 128), 256>>>(ao, wo, out, NTOK, HIDDIM, VVDIM);
}

// round 6
// speedup vs baseline: 1.3851x; 1.3851x over previous
#include <cuda_runtime.h>
#include <cuda_bf16.h>
#include <mma.h>
#include <math.h>
#include <stdint.h>

using namespace nvcuda;

// ---------------- problem constants ----------------
#define NTOK   4096            // B*S
#define HIDDIM 2048
#define QLR    1536
#define KVLR   512
#define HEADS  16
#define NOPE   128
#define ROPED  64
#define HD     192             // NOPE+ROPE
#define VDIM   128
#define SEQ    1024
#define BATCH  4
#define QDIM   (HEADS*HD)      // 3072
#define KVDIM  (KVLR+ROPED)    // 576
#define KVPAD  640             // padded kv width (multiple of 128)
#define KNOPE_DIM (HEADS*NOPE) // 2048
#define VVDIM  (HEADS*VDIM)    // 2048

// ---------------- device scratch (fp32 only, as in R1) ----------------
__device__ float g_qa   [(size_t)NTOK*QLR];
__device__ float g_q    [(size_t)NTOK*QDIM];
__device__ float g_kv   [(size_t)NTOK*KVPAD];
__device__ float g_ckv  [(size_t)NTOK*KVLR];
__device__ float g_kpe  [(size_t)NTOK*ROPED];
__device__ float g_knope[(size_t)NTOK*KNOPE_DIM];
__device__ float g_v    [(size_t)NTOK*VVDIM];
__device__ float g_ao   [(size_t)NTOK*VVDIM];

// ---------------- block reduce ----------------
__device__ __forceinline__ float block_sum256(float v) {
    __shared__ float red[8];
    int lane = threadIdx.x & 31, w = threadIdx.x >> 5;
    #pragma unroll
    for (int o = 16; o; o >>= 1) v += __shfl_xor_sync(0xffffffffu, v, o);
    if (lane == 0) red[w] = v;
    __syncthreads();
    if (threadIdx.x == 0) {
        float t = 0.f;
        #pragma unroll
        for (int i = 0; i < 8; i++) t += red[i];
        red[0] = t;
    }
    __syncthreads();
    return red[0];
}

// ================= WMMA split-bf16 GEMM (fp32 in / fp32 out) =================
// C[M,Nalloc] = A[M,K] @ B[Nvalid,K]^T with A,B split to bf16 hi+lo in-kernel.
// 3-term product (hi*hi + hi*lo + lo*hi), err ~1.5e-5.
// CTA 128x128, BK=64, 8 warps (2m x 4n -> warp tile 64x32).
#define GBM 128
#define GBN 128
#define GBK 64
#define SPAD 80                       // bf16 elems; 160B rows -> 32B-aligned fragments
#define TILE_E (128*SPAD)             // 10240 elems per tile
#define GEMM_SMEM (4*TILE_E*2)        // 81920 bytes

__global__ __launch_bounds__(256) void gemm_wmma(
    const float* __restrict__ A, const float* __restrict__ B,
    float* __restrict__ C, int M, int Nalloc, int Nvalid, int K)
{
    extern __shared__ __align__(32) char gsm[];
    __nv_bfloat16* sAhi = (__nv_bfloat16*)gsm;
    __nv_bfloat16* sAlo = sAhi + TILE_E;
    __nv_bfloat16* sBhi = sAhi + 2 * TILE_E;
    __nv_bfloat16* sBlo = sAhi + 3 * TILE_E;

    const int tid = threadIdx.x, wid = tid >> 5;
    const int warp_m = wid >> 2;      // 0..1
    const int warp_n = wid & 3;       // 0..3
    const int bm = blockIdx.y * GBM, bn = blockIdx.x * GBN;
    const int nch = K / GBK;

    wmma::fragment<wmma::accumulator, 16, 16, 16, float> facc[4][2];
    #pragma unroll
    for (int mi = 0; mi < 4; mi++)
        #pragma unroll
        for (int ni = 0; ni < 2; ni++) wmma::fill_fragment(facc[mi][ni], 0.0f);

    for (int c = 0; c < nch; c++) {
        const int k0 = c * GBK;
        // ---- stage: load fp32, split to bf16 hi/lo, store to smem ----
        #pragma unroll
        for (int it = 0; it < 4; it++) {
            int idx = tid + it * 256;           // 0..1023
            int r = idx >> 3, ch = idx & 7;     // r 0..127, ch 0..7 (8 floats each)
            {
                const float* src = A + (size_t)(bm + r) * K + k0 + ch * 8;
                float4 v0 = *(const float4*)src;
                float4 v1 = *(const float4*)(src + 4);
                float vv[8] = {v0.x, v0.y, v0.z, v0.w, v1.x, v1.y, v1.z, v1.w};
                __align__(16) __nv_bfloat16 h[8], l[8];
                #pragma unroll
                for (int e = 0; e < 8; e++) {
                    h[e] = __float2bfloat16(vv[e]);
                    l[e] = __float2bfloat16(vv[e] - __bfloat162float(h[e]));
                }
                *(uint4*)(sAhi + r * SPAD + ch * 8) = *(uint4*)h;
                *(uint4*)(sAlo + r * SPAD + ch * 8) = *(uint4*)l;
            }
            {
                int gn = bn + r; if (gn >= Nvalid) gn = Nvalid - 1;  // clamp: pad cols never read
                const float* src = B + (size_t)gn * K + k0 + ch * 8;
                float4 v0 = *(const float4*)src;
                float4 v1 = *(const float4*)(src + 4);
                float vv[8] = {v0.x, v0.y, v0.z, v0.w, v1.x, v1.y, v1.z, v1.w};
                __align__(16) __nv_bfloat16 h[8], l[8];
                #pragma unroll
                for (int e = 0; e < 8; e++) {
                    h[e] = __float2bfloat16(vv[e]);
                    l[e] = __float2bfloat16(vv[e] - __bfloat162float(h[e]));
                }
                *(uint4*)(sBhi + r * SPAD + ch * 8) = *(uint4*)h;
                *(uint4*)(sBlo + r * SPAD + ch * 8) = *(uint4*)l;
            }
        }
        __syncthreads();

        // ---- compute ----
        #pragma unroll
        for (int kk = 0; kk < GBK; kk += 16) {
            wmma::fragment<wmma::matrix_a, 16, 16, 16, __nv_bfloat16, wmma::row_major> fah[4], fal[4];
            #pragma unroll
            for (int mi = 0; mi < 4; mi++) {
                int row = warp_m * 64 + mi * 16;
                wmma::load_matrix_sync(fah[mi], sAhi + row * SPAD + kk, SPAD);
                wmma::load_matrix_sync(fal[mi], sAlo + row * SPAD + kk, SPAD);
            }
            #pragma unroll
            for (int ni = 0; ni < 2; ni++) {
                int col = warp_n * 32 + ni * 16;
                wmma::fragment<wmma::matrix_b, 16, 16, 16, __nv_bfloat16, wmma::col_major> fbh, fbl;
                // B stored [N,K] row-major == B^T (k,n) col-major with ldm=SPAD
                wmma::load_matrix_sync(fbh, sBhi + col * SPAD + kk, SPAD);
                wmma::load_matrix_sync(fbl, sBlo + col * SPAD + kk, SPAD);
                #pragma unroll
                for (int mi = 0; mi < 4; mi++) {
                    wmma::mma_sync(facc[mi][ni], fah[mi], fbh, facc[mi][ni]);
                    wmma::mma_sync(facc[mi][ni], fah[mi], fbl, facc[mi][ni]);
                    wmma::mma_sync(facc[mi][ni], fal[mi], fbh, facc[mi][ni]);
                }
            }
        }
        __syncthreads();
    }

    // ---- epilogue: Nalloc multiple of 128, unguarded wmma store ----
    #pragma unroll
    for (int mi = 0; mi < 4; mi++) {
        int row = bm + warp_m * 64 + mi * 16;
        #pragma unroll
        for (int ni = 0; ni < 2; ni++) {
            int col = bn + warp_n * 32 + ni * 16;
            wmma::store_matrix_sync(C + (size_t)row * Nalloc + col, facc[mi][ni],
                                    Nalloc, wmma::mem_row_major);
        }
    }
}

// ---------------- rmsnorm (full row, in place ok) ----------------
__global__ void rmsnorm_k(const float* __restrict__ in, const float* __restrict__ w,
                          float* __restrict__ out, int len)
{
    int row = blockIdx.x;
    const float* h = in + (size_t)row * len;
    float ss = 0.f;
    for (int i = threadIdx.x; i < len; i += blockDim.x) { float v = h[i]; ss += v * v; }
    ss = block_sum256(ss);
    float sc = rsqrtf(ss / (float)len + 1e-6f);
    float* o = out + (size_t)row * len;
    for (int i = threadIdx.x; i < len; i += blockDim.x) o[i] = h[i] * sc * w[i];
}

// ---------------- kv split: rmsnorm first 512 -> ckv ; rope last 64 -> kpe ----------------
__global__ void kv_norm_rope_k(const float* __restrict__ w,
                               const float* __restrict__ sin_t,
                               const float* __restrict__ cos_t)
{
    int row = blockIdx.x;
    const float* h = g_kv + (size_t)row * KVPAD;   // padded stride
    float ss = 0.f;
    for (int i = threadIdx.x; i < KVLR; i += blockDim.x) { float v = h[i]; ss += v * v; }
    ss = block_sum256(ss);
    float sc = rsqrtf(ss / (float)KVLR + 1e-6f);
    for (int i = threadIdx.x; i < KVLR; i += blockDim.x)
        g_ckv[(size_t)row * KVLR + i] = h[i] * sc * w[i];
    if (threadIdx.x < ROPED / 2) {
        int i = threadIdx.x;
        int pos = row & (SEQ - 1);
        float s = sin_t[pos * 32 + i], c = cos_t[pos * 32 + i];
        float e = h[KVLR + 2 * i], o = h[KVLR + 2 * i + 1];
        g_kpe[(size_t)row * ROPED + 2 * i]     = e * c - o * s;
        g_kpe[(size_t)row * ROPED + 2 * i + 1] = e * s + o * c;
    }
}

// ---------------- rope on q_pe (in place on g_q) ----------------
__global__ void q_rope_k(const float* __restrict__ sin_t, const float* __restrict__ cos_t)
{
    int idx = blockIdx.x * blockDim.x + threadIdx.x;
    if (idx >= NTOK * HEADS * (ROPED / 2)) return;
    int i   = idx & 31;
    int hh  = (idx >> 5) & 15;
    int row = idx >> 9;
    int pos = row & (SEQ - 1);
    float* p = g_q + (size_t)row * QDIM + hh * HD + NOPE + 2 * i;
    float s = sin_t[pos * 32 + i], c = cos_t[pos * 32 + i];
    float e = p[0], o = p[1];
    p[0] = e * c - o * s;
    p[1] = e * s + o * c;
}

// ---------------- flash attention (causal, fp32) — verbatim from R1 ----------------
#define AT_THREADS 256
#define QKSTR 196
#define PSTR  65

__global__ __launch_bounds__(AT_THREADS) void attn_k()
{
    extern __shared__ float smf[];
    float* Qs   = smf;
    float* Ks   = Qs + 64 * QKSTR;
    float* Vs   = Ks + 64 * QKSTR;
    float* Ps   = Vs + 64 * VDIM;
    float* mrow = Ps + 64 * PSTR;
    float* lrow = mrow + 64;
    float* arow = lrow + 64;

    const int qt = blockIdx.x, hh = blockIdx.y, b = blockIdx.z;
    const int tid = threadIdx.x;
    const int q0 = qt * 64;
    const int grow0 = b * SEQ + q0;

    for (int t = tid; t < 64 * 48; t += AT_THREADS) {
        int r = t / 48, c = t % 48;
        float4 v = *(const float4*)(g_q + (size_t)(grow0 + r) * QDIM + hh * HD + c * 4);
        *(float4*)&Qs[r * QKSTR + c * 4] = v;
    }
    if (tid < 64) { mrow[tid] = -INFINITY; lrow[tid] = 0.f; }

    float4 O4[8];
    #pragma unroll
    for (int k = 0; k < 8; k++) O4[k] = make_float4(0.f, 0.f, 0.f, 0.f);

    const int tx = tid & 15, ty = tid >> 4;
    const int pr = tid >> 2;
    const int cb = (tid & 3) * 4;

    __syncthreads();

    const float scale = 0.07216878364870323f;

    for (int kt = 0; kt <= qt; kt++) {
        const int k0 = kt * 64;
        const int gk0 = b * SEQ + k0;

        for (int t = tid; t < 64 * 48; t += AT_THREADS) {
            int r = t / 48, c = t % 48;
            float4 v;
            if (c < 32)
                v = *(const float4*)(g_knope + (size_t)(gk0 + r) * KNOPE_DIM + hh * NOPE + c * 4);
            else
                v = *(const float4*)(g_kpe + (size_t)(gk0 + r) * ROPED + (c - 32) * 4);
            *(float4*)&Ks[r * QKSTR + c * 4] = v;
        }
        for (int t = tid; t < 64 * 32; t += AT_THREADS) {
            int r = t / 32, c = t % 32;
            *(float4*)&Vs[r * VDIM + c * 4] =
                *(const float4*)(g_v + (size_t)(gk0 + r) * VVDIM + hh * VDIM + c * 4);
        }
        __syncthreads();

        float sacc[4][4] = {};
        #pragma unroll 4
        for (int d = 0; d < HD; d += 4) {
            float4 qv[4], kv4[4];
            #pragma unroll
            for (int ii = 0; ii < 4; ii++) qv[ii]  = *(float4*)&Qs[(ty * 4 + ii) * QKSTR + d];
            #pragma unroll
            for (int jj = 0; jj < 4; jj++) kv4[jj] = *(float4*)&Ks[(tx + 16 * jj) * QKSTR + d];
            #pragma unroll
            for (int ii = 0; ii < 4; ii++)
                #pragma unroll
                for (int jj = 0; jj < 4; jj++)
                    sacc[ii][jj] += qv[ii].x * kv4[jj].x + qv[ii].y * kv4[jj].y
                                  + qv[ii].z * kv4[jj].z + qv[ii].w * kv4[jj].w;
        }
        #pragma unroll
        for (int ii = 0; ii < 4; ii++)
            #pragma unroll
            for (int jj = 0; jj < 4; jj++) {
                int qi = q0 + ty * 4 + ii;
                int kj = k0 + tx + 16 * jj;
                Ps[(ty * 4 + ii) * PSTR + tx + 16 * jj] =
                    (kj <= qi) ? sacc[ii][jj] * scale : -1e30f;
            }
        __syncthreads();

        {
            int lane = tid & 31;
            int rbase = (tid >> 5) * 8;
            #pragma unroll
            for (int rr = 0; rr < 8; rr++) {
                int r = rbase + rr;
                float v0 = Ps[r * PSTR + lane];
                float v1 = Ps[r * PSTR + 32 + lane];
                float mx = fmaxf(v0, v1);
                #pragma unroll
                for (int o = 16; o; o >>= 1) mx = fmaxf(mx, __shfl_xor_sync(0xffffffffu, mx, o));
                float mold = mrow[r];
                float mnew = fmaxf(mold, mx);
                float p0 = __expf(v0 - mnew), p1 = __expf(v1 - mnew);
                Ps[r * PSTR + lane] = p0;
                Ps[r * PSTR + 32 + lane] = p1;
                float s = p0 + p1;
                #pragma unroll
                for (int o = 16; o; o >>= 1) s += __shfl_xor_sync(0xffffffffu, s, o);
                if (lane == 0) {
                    float a = (mold > -1e30f) ? __expf(mold - mnew) : 0.f;
                    arow[r] = a;
                    lrow[r] = lrow[r] * a + s;
                    mrow[r] = mnew;
                }
            }
        }
        __syncthreads();

        {
            float a = arow[pr];
            #pragma unroll
            for (int k = 0; k < 8; k++) {
                O4[k].x *= a; O4[k].y *= a; O4[k].z *= a; O4[k].w *= a;
            }
            #pragma unroll 2
            for (int j = 0; j < 64; j++) {
                float p = Ps[pr * PSTR + j];
                #pragma unroll
                for (int k = 0; k < 8; k++) {
                    float4 v = *(float4*)&Vs[j * VDIM + cb + 16 * k];
                    O4[k].x = fmaf(p, v.x, O4[k].x);
                    O4[k].y = fmaf(p, v.y, O4[k].y);
                    O4[k].z = fmaf(p, v.z, O4[k].z);
                    O4[k].w = fmaf(p, v.w, O4[k].w);
                }
            }
        }
        __syncthreads();
    }

    float inv = 1.f / lrow[pr];
    #pragma unroll
    for (int k = 0; k < 8; k++) {
        float4 v = make_float4(O4[k].x * inv, O4[k].y * inv, O4[k].z * inv, O4[k].w * inv);
        *(float4*)(g_ao + (size_t)(grow0 + pr) * VVDIM + hh * VDIM + cb + 16 * k) = v;
    }
}

// ================= host launch =================
static inline void launch_gemm(const float* a, const float* b, float* c,
                               int M, int Nalloc, int Nvalid, int K)
{
    dim3 grid(Nalloc / GBN, M / GBM);
    gemm_wmma<<<grid, 256, GEMM_SMEM>>>(a, b, c, M, Nalloc, Nvalid, K);
}

extern "C" void kernel_launch(void* const* d_in, const int* in_sizes, int n_in,
                              void* d_out, int out_size)
{
    const float* x        = (const float*)d_in[0];
    const float* wq_a     = (const float*)d_in[1];
    const float* w_qa_ln  = (const float*)d_in[2];
    const float* wq_b     = (const float*)d_in[3];
    const float* wkv_a    = (const float*)d_in[4];
    const float* w_kva_ln = (const float*)d_in[5];
    const float* wk_b     = (const float*)d_in[6];
    const float* wv_b     = (const float*)d_in[7];
    const float* wo       = (const float*)d_in[8];
    const float* rsin     = (const float*)d_in[9];
    const float* rcos     = (const float*)d_in[10];
    float* out = (float*)d_out;

    float *qa, *q, *kv, *ckv, *knope, *v, *ao;
    cudaGetSymbolAddress((void**)&qa,    g_qa);
    cudaGetSymbolAddress((void**)&q,     g_q);
    cudaGetSymbolAddress((void**)&kv,    g_kv);
    cudaGetSymbolAddress((void**)&ckv,   g_ckv);
    cudaGetSymbolAddress((void**)&knope, g_knope);
    cudaGetSymbolAddress((void**)&v,     g_v);
    cudaGetSymbolAddress((void**)&ao,    g_ao);

    cudaFuncSetAttribute(gemm_wmma, cudaFuncAttributeMaxDynamicSharedMemorySize, GEMM_SMEM);

    // q_a = x @ wq_a^T ; rmsnorm ; q = q_a @ wq_b^T
    launch_gemm(x, wq_a, qa, NTOK, QLR, QLR, HIDDIM);
    rmsnorm_k<<<NTOK, 256>>>(qa, w_qa_ln, qa, QLR);
    launch_gemm(qa, wq_b, q, NTOK, QDIM, QDIM, QLR);

    // kv = x @ wkv_a^T (padded to 640 cols) ; split norm + k_pe rope
    launch_gemm(x, wkv_a, kv, NTOK, KVPAD, KVDIM, HIDDIM);
    kv_norm_rope_k<<<NTOK, 256>>>(w_kva_ln, rsin, rcos);

    // k_nope = ckv @ wk_b^T ; v = ckv @ wv_b^T
    launch_gemm(ckv, wk_b, knope, NTOK, KNOPE_DIM, KNOPE_DIM, KVLR);
    launch_gemm(ckv, wv_b, v, NTOK, VVDIM, VVDIM, KVLR);

    // rope on q_pe
    q_rope_k<<<(NTOK * HEADS * 32 + 255) / 256, 256>>>(rsin, rcos);

    // attention
    size_t shm = (size_t)(2 * 64 * QKSTR + 64 * VDIM + 64 * PSTR + 192) * sizeof(float);
    cudaFuncSetAttribute(attn_k, cudaFuncAttributeMaxDynamicSharedMemorySize, (int)shm);
    attn_k<<<dim3(SEQ / 64, HEADS, BATCH), AT_THREADS, shm>>>();

    // out = ao @ wo^T
    launch_gemm(ao, wo, out, NTOK, HIDDIM, HIDDIM, VVDIM);
}

// round 7
// speedup vs baseline: 1.4217x; 1.0264x over previous
#include <cuda_runtime.h>
#include <cuda_bf16.h>
#include <mma.h>
#include <math.h>
#include <stdint.h>

using namespace nvcuda;

// ---------------- problem constants ----------------
#define NTOK   4096            // B*S
#define HIDDIM 2048
#define QLR    1536
#define KVLR   512
#define HEADS  16
#define NOPE   128
#define ROPED  64
#define HD     192             // NOPE+ROPE
#define VDIM   128
#define SEQ    1024
#define BATCH  4
#define QDIM   (HEADS*HD)      // 3072
#define KVDIM  (KVLR+ROPED)    // 576
#define KVPAD  640             // padded kv width (multiple of 128)
#define KNOPE_DIM (HEADS*NOPE) // 2048
#define VVDIM  (HEADS*VDIM)    // 2048

// ---------------- device scratch (fp32 only) ----------------
__device__ float g_qa   [(size_t)NTOK*QLR];
__device__ float g_q    [(size_t)NTOK*QDIM];
__device__ float g_kv   [(size_t)NTOK*KVPAD];
__device__ float g_ckv  [(size_t)NTOK*KVLR];
__device__ float g_kpe  [(size_t)NTOK*ROPED];
__device__ float g_knope[(size_t)NTOK*KNOPE_DIM];
__device__ float g_v    [(size_t)NTOK*VVDIM];
__device__ float g_ao   [(size_t)NTOK*VVDIM];

// ---------------- block reduce ----------------
__device__ __forceinline__ float block_sum256(float v) {
    __shared__ float red[8];
    int lane = threadIdx.x & 31, w = threadIdx.x >> 5;
    #pragma unroll
    for (int o = 16; o; o >>= 1) v += __shfl_xor_sync(0xffffffffu, v, o);
    if (lane == 0) red[w] = v;
    __syncthreads();
    if (threadIdx.x == 0) {
        float t = 0.f;
        #pragma unroll
        for (int i = 0; i < 8; i++) t += red[i];
        red[0] = t;
    }
    __syncthreads();
    return red[0];
}

// ================= WMMA split-bf16 GEMM, double-buffered =================
// C[M,Nalloc] = A[M,K] @ B[Nvalid,K]^T; in-kernel bf16 hi/lo split; 3-term product.
// CTA 128x128, BK=64, 8 warps (2m x 4n). 2-stage smem pipeline + reg prefetch.
#define GBM 128
#define GBN 128
#define GBK 64
#define SPAD 80                       // bf16 elems; 160B rows -> 32B-aligned fragments
#define TILE_E (128*SPAD)             // 10240 elems per tile
#define STAGE_E (4*TILE_E)            // 4 tiles per stage
#define GEMM_SMEM (2*STAGE_E*2)       // 163840 bytes

__global__ __launch_bounds__(256) void gemm_wmma(
    const float* __restrict__ A, const float* __restrict__ B,
    float* __restrict__ C, int M, int Nalloc, int Nvalid, int K)
{
    extern __shared__ __align__(32) char gsm[];
    __nv_bfloat16* smb = (__nv_bfloat16*)gsm;

    const int tid = threadIdx.x, wid = tid >> 5;
    const int warp_m = wid >> 2;      // 0..1
    const int warp_n = wid & 3;       // 0..3
    const int bm = blockIdx.y * GBM, bn = blockIdx.x * GBN;
    const int nch = K / GBK;

    // staging map: idx = tid + it*256; r = idx>>3 (0..127), ch = idx&7 (8 floats)
    const int sr = tid >> 3;          // rows sr, sr+32, sr+64, sr+96
    const int sc = tid & 7;

    float4 rA[4][2], rB[4][2];        // fp32 staged regs (64 floats)

    auto ldg_stage = [&](int c) {
        const int k0 = c * GBK;
        #pragma unroll
        for (int it = 0; it < 4; it++) {
            int r = sr + it * 32;
            const float* srcA = A + (size_t)(bm + r) * K + k0 + sc * 8;
            rA[it][0] = *(const float4*)srcA;
            rA[it][1] = *(const float4*)(srcA + 4);
            int gn = bn + r; if (gn >= Nvalid) gn = Nvalid - 1;  // clamp; pad cols never read
            const float* srcB = B + (size_t)gn * K + k0 + sc * 8;
            rB[it][0] = *(const float4*)srcB;
            rB[it][1] = *(const float4*)(srcB + 4);
        }
    };
    auto cvt_sts = [&](int s) {
        __nv_bfloat16* sAhi = smb + s * STAGE_E;
        __nv_bfloat16* sAlo = sAhi + TILE_E;
        __nv_bfloat16* sBhi = sAhi + 2 * TILE_E;
        __nv_bfloat16* sBlo = sAhi + 3 * TILE_E;
        #pragma unroll
        for (int it = 0; it < 4; it++) {
            int r = sr + it * 32;
            int e = r * SPAD + sc * 8;
            {
                float vv[8] = {rA[it][0].x, rA[it][0].y, rA[it][0].z, rA[it][0].w,
                               rA[it][1].x, rA[it][1].y, rA[it][1].z, rA[it][1].w};
                __align__(16) __nv_bfloat16 h[8], l[8];
                #pragma unroll
                for (int q = 0; q < 8; q++) {
                    h[q] = __float2bfloat16(vv[q]);
                    l[q] = __float2bfloat16(vv[q] - __bfloat162float(h[q]));
                }
                *(uint4*)(sAhi + e) = *(uint4*)h;
                *(uint4*)(sAlo + e) = *(uint4*)l;
            }
            {
                float vv[8] = {rB[it][0].x, rB[it][0].y, rB[it][0].z, rB[it][0].w,
                               rB[it][1].x, rB[it][1].y, rB[it][1].z, rB[it][1].w};
                __align__(16) __nv_bfloat16 h[8], l[8];
                #pragma unroll
                for (int q = 0; q < 8; q++) {
                    h[q] = __float2bfloat16(vv[q]);
                    l[q] = __float2bfloat16(vv[q] - __bfloat162float(h[q]));
                }
                *(uint4*)(sBhi + e) = *(uint4*)h;
                *(uint4*)(sBlo + e) = *(uint4*)l;
            }
        }
    };

    wmma::fragment<wmma::accumulator, 16, 16, 16, float> facc[4][2];
    #pragma unroll
    for (int mi = 0; mi < 4; mi++)
        #pragma unroll
        for (int ni = 0; ni < 2; ni++) wmma::fill_fragment(facc[mi][ni], 0.0f);

    ldg_stage(0);
    cvt_sts(0);

    for (int c = 0; c < nch; c++) {
        if (c + 1 < nch) ldg_stage(c + 1);     // start next chunk's LDGs early
        __syncthreads();                        // stage c&1 visible; prev reads done

        const int s = c & 1;
        __nv_bfloat16* sAhi = smb + s * STAGE_E;
        __nv_bfloat16* sAlo = sAhi + TILE_E;
        __nv_bfloat16* sBhi = sAhi + 2 * TILE_E;
        __nv_bfloat16* sBlo = sAhi + 3 * TILE_E;

        #pragma unroll
        for (int kk = 0; kk < GBK; kk += 16) {
            wmma::fragment<wmma::matrix_a, 16, 16, 16, __nv_bfloat16, wmma::row_major> fah[4], fal[4];
            #pragma unroll
            for (int mi = 0; mi < 4; mi++) {
                int row = warp_m * 64 + mi * 16;
                wmma::load_matrix_sync(fah[mi], sAhi + row * SPAD + kk, SPAD);
                wmma::load_matrix_sync(fal[mi], sAlo + row * SPAD + kk, SPAD);
            }
            #pragma unroll
            for (int ni = 0; ni < 2; ni++) {
                int col = warp_n * 32 + ni * 16;
                wmma::fragment<wmma::matrix_b, 16, 16, 16, __nv_bfloat16, wmma::col_major> fbh, fbl;
                wmma::load_matrix_sync(fbh, sBhi + col * SPAD + kk, SPAD);
                wmma::load_matrix_sync(fbl, sBlo + col * SPAD + kk, SPAD);
                #pragma unroll
                for (int mi = 0; mi < 4; mi++) {
                    wmma::mma_sync(facc[mi][ni], fah[mi], fbh, facc[mi][ni]);
                    wmma::mma_sync(facc[mi][ni], fah[mi], fbl, facc[mi][ni]);
                    wmma::mma_sync(facc[mi][ni], fal[mi], fbh, facc[mi][ni]);
                }
            }
        }
        if (c + 1 < nch) cvt_sts((c + 1) & 1);  // write other buffer; safe (all readers past sync)
    }

    // ---- epilogue: Nalloc multiple of 128, unguarded wmma store ----
    #pragma unroll
    for (int mi = 0; mi < 4; mi++) {
        int row = bm + warp_m * 64 + mi * 16;
        #pragma unroll
        for (int ni = 0; ni < 2; ni++) {
            int col = bn + warp_n * 32 + ni * 16;
            wmma::store_matrix_sync(C + (size_t)row * Nalloc + col, facc[mi][ni],
                                    Nalloc, wmma::mem_row_major);
        }
    }
}

// ---------------- rmsnorm ----------------
__global__ void rmsnorm_k(const float* __restrict__ in, const float* __restrict__ w,
                          float* __restrict__ out, int len)
{
    int row = blockIdx.x;
    const float* h = in + (size_t)row * len;
    float ss = 0.f;
    for (int i = threadIdx.x; i < len; i += blockDim.x) { float v = h[i]; ss += v * v; }
    ss = block_sum256(ss);
    float sc = rsqrtf(ss / (float)len + 1e-6f);
    float* o = out + (size_t)row * len;
    for (int i = threadIdx.x; i < len; i += blockDim.x) o[i] = h[i] * sc * w[i];
}

// ---------------- kv split: rmsnorm first 512 -> ckv ; rope last 64 -> kpe ----------------
__global__ void kv_norm_rope_k(const float* __restrict__ w,
                               const float* __restrict__ sin_t,
                               const float* __restrict__ cos_t)
{
    int row = blockIdx.x;
    const float* h = g_kv + (size_t)row * KVPAD;
    float ss = 0.f;
    for (int i = threadIdx.x; i < KVLR; i += blockDim.x) { float v = h[i]; ss += v * v; }
    ss = block_sum256(ss);
    float sc = rsqrtf(ss / (float)KVLR + 1e-6f);
    for (int i = threadIdx.x; i < KVLR; i += blockDim.x)
        g_ckv[(size_t)row * KVLR + i] = h[i] * sc * w[i];
    if (threadIdx.x < ROPED / 2) {
        int i = threadIdx.x;
        int pos = row & (SEQ - 1);
        float s = sin_t[pos * 32 + i], c = cos_t[pos * 32 + i];
        float e = h[KVLR + 2 * i], o = h[KVLR + 2 * i + 1];
        g_kpe[(size_t)row * ROPED + 2 * i]     = e * c - o * s;
        g_kpe[(size_t)row * ROPED + 2 * i + 1] = e * s + o * c;
    }
}

// ---------------- rope on q_pe (in place on g_q) ----------------
__global__ void q_rope_k(const float* __restrict__ sin_t, const float* __restrict__ cos_t)
{
    int idx = blockIdx.x * blockDim.x + threadIdx.x;
    if (idx >= NTOK * HEADS * (ROPED / 2)) return;
    int i   = idx & 31;
    int hh  = (idx >> 5) & 15;
    int row = idx >> 9;
    int pos = row & (SEQ - 1);
    float* p = g_q + (size_t)row * QDIM + hh * HD + NOPE + 2 * i;
    float s = sin_t[pos * 32 + i], c = cos_t[pos * 32 + i];
    float e = p[0], o = p[1];
    p[0] = e * c - o * s;
    p[1] = e * s + o * c;
}

// ---------------- flash attention (causal, fp32) ----------------
#define AT_THREADS 256
#define QKSTR 196
#define PSTR  65

__global__ __launch_bounds__(AT_THREADS) void attn_k()
{
    extern __shared__ float smf[];
    float* Qs   = smf;
    float* Ks   = Qs + 64 * QKSTR;
    float* Vs   = Ks + 64 * QKSTR;
    float* Ps   = Vs + 64 * VDIM;
    float* mrow = Ps + 64 * PSTR;
    float* lrow = mrow + 64;
    float* arow = lrow + 64;

    const int qt = blockIdx.x, hh = blockIdx.y, b = blockIdx.z;
    const int tid = threadIdx.x;
    const int q0 = qt * 64;
    const int grow0 = b * SEQ + q0;

    for (int t = tid; t < 64 * 48; t += AT_THREADS) {
        int r = t / 48, c = t % 48;
        float4 v = *(const float4*)(g_q + (size_t)(grow0 + r) * QDIM + hh * HD + c * 4);
        *(float4*)&Qs[r * QKSTR + c * 4] = v;
    }
    if (tid < 64) { mrow[tid] = -INFINITY; lrow[tid] = 0.f; }

    float4 O4[8];
    #pragma unroll
    for (int k = 0; k < 8; k++) O4[k] = make_float4(0.f, 0.f, 0.f, 0.f);

    const int tx = tid & 15, ty = tid >> 4;
    const int pr = tid >> 2;
    const int cb = (tid & 3) * 4;

    __syncthreads();

    const float scale = 0.07216878364870323f;

    for (int kt = 0; kt <= qt; kt++) {
        const int k0 = kt * 64;
        const int gk0 = b * SEQ + k0;

        for (int t = tid; t < 64 * 48; t += AT_THREADS) {
            int r = t / 48, c = t % 48;
            float4 v;
            if (c < 32)
                v = *(const float4*)(g_knope + (size_t)(gk0 + r) * KNOPE_DIM + hh * NOPE + c * 4);
            else
                v = *(const float4*)(g_kpe + (size_t)(gk0 + r) * ROPED + (c - 32) * 4);
            *(float4*)&Ks[r * QKSTR + c * 4] = v;
        }
        for (int t = tid; t < 64 * 32; t += AT_THREADS) {
            int r = t / 32, c = t % 32;
            *(float4*)&Vs[r * VDIM + c * 4] =
                *(const float4*)(g_v + (size_t)(gk0 + r) * VVDIM + hh * VDIM + c * 4);
        }
        __syncthreads();

        float sacc[4][4] = {};
        #pragma unroll 4
        for (int d = 0; d < HD; d += 4) {
            float4 qv[4], kv4[4];
            #pragma unroll
            for (int ii = 0; ii < 4; ii++) qv[ii]  = *(float4*)&Qs[(ty * 4 + ii) * QKSTR + d];
            #pragma unroll
            for (int jj = 0; jj < 4; jj++) kv4[jj] = *(float4*)&Ks[(tx + 16 * jj) * QKSTR + d];
            #pragma unroll
            for (int ii = 0; ii < 4; ii++)
                #pragma unroll
                for (int jj = 0; jj < 4; jj++)
                    sacc[ii][jj] += qv[ii].x * kv4[jj].x + qv[ii].y * kv4[jj].y
                                  + qv[ii].z * kv4[jj].z + qv[ii].w * kv4[jj].w;
        }
        #pragma unroll
        for (int ii = 0; ii < 4; ii++)
            #pragma unroll
            for (int jj = 0; jj < 4; jj++) {
                int qi = q0 + ty * 4 + ii;
                int kj = k0 + tx + 16 * jj;
                Ps[(ty * 4 + ii) * PSTR + tx + 16 * jj] =
                    (kj <= qi) ? sacc[ii][jj] * scale : -1e30f;
            }
        __syncthreads();

        {
            int lane = tid & 31;
            int rbase = (tid >> 5) * 8;
            #pragma unroll
            for (int rr = 0; rr < 8; rr++) {
                int r = rbase + rr;
                float v0 = Ps[r * PSTR + lane];
                float v1 = Ps[r * PSTR + 32 + lane];
                float mx = fmaxf(v0, v1);
                #pragma unroll
                for (int o = 16; o; o >>= 1) mx = fmaxf(mx, __shfl_xor_sync(0xffffffffu, mx, o));
                float mold = mrow[r];
                float mnew = fmaxf(mold, mx);
                float p0 = __expf(v0 - mnew), p1 = __expf(v1 - mnew);
                Ps[r * PSTR + lane] = p0;
                Ps[r * PSTR + 32 + lane] = p1;
                float s = p0 + p1;
                #pragma unroll
                for (int o = 16; o; o >>= 1) s += __shfl_xor_sync(0xffffffffu, s, o);
                if (lane == 0) {
                    float a = (mold > -1e30f) ? __expf(mold - mnew) : 0.f;
                    arow[r] = a;
                    lrow[r] = lrow[r] * a + s;
                    mrow[r] = mnew;
                }
            }
        }
        __syncthreads();

        {
            float a = arow[pr];
            #pragma unroll
            for (int k = 0; k < 8; k++) {
                O4[k].x *= a; O4[k].y *= a; O4[k].z *= a; O4[k].w *= a;
            }
            #pragma unroll 2
            for (int j = 0; j < 64; j++) {
                float p = Ps[pr * PSTR + j];
                #pragma unroll
                for (int k = 0; k < 8; k++) {
                    float4 v = *(float4*)&Vs[j * VDIM + cb + 16 * k];
                    O4[k].x = fmaf(p, v.x, O4[k].x);
                    O4[k].y = fmaf(p, v.y, O4[k].y);
                    O4[k].z = fmaf(p, v.z, O4[k].z);
                    O4[k].w = fmaf(p, v.w, O4[k].w);
                }
            }
        }
        __syncthreads();
    }

    float inv = 1.f / lrow[pr];
    #pragma unroll
    for (int k = 0; k < 8; k++) {
        float4 v = make_float4(O4[k].x * inv, O4[k].y * inv, O4[k].z * inv, O4[k].w * inv);
        *(float4*)(g_ao + (size_t)(grow0 + pr) * VVDIM + hh * VDIM + cb + 16 * k) = v;
    }
}

// ================= host launch =================
static inline void launch_gemm(const float* a, const float* b, float* c,
                               int M, int Nalloc, int Nvalid, int K)
{
    dim3 grid(Nalloc / GBN, M / GBM);
    gemm_wmma<<<grid, 256, GEMM_SMEM>>>(a, b, c, M, Nalloc, Nvalid, K);
}

extern "C" void kernel_launch(void* const* d_in, const int* in_sizes, int n_in,
                              void* d_out, int out_size)
{
    const float* x        = (const float*)d_in[0];
    const float* wq_a     = (const float*)d_in[1];
    const float* w_qa_ln  = (const float*)d_in[2];
    const float* wq_b     = (const float*)d_in[3];
    const float* wkv_a    = (const float*)d_in[4];
    const float* w_kva_ln = (const float*)d_in[5];
    const float* wk_b     = (const float*)d_in[6];
    const float* wv_b     = (const float*)d_in[7];
    const float* wo       = (const float*)d_in[8];
    const float* rsin     = (const float*)d_in[9];
    const float* rcos     = (const float*)d_in[10];
    float* out = (float*)d_out;

    float *qa, *q, *kv, *ckv, *knope, *v, *ao;
    cudaGetSymbolAddress((void**)&qa,    g_qa);
    cudaGetSymbolAddress((void**)&q,     g_q);
    cudaGetSymbolAddress((void**)&kv,    g_kv);
    cudaGetSymbolAddress((void**)&ckv,   g_ckv);
    cudaGetSymbolAddress((void**)&knope, g_knope);
    cudaGetSymbolAddress((void**)&v,     g_v);
    cudaGetSymbolAddress((void**)&ao,    g_ao);

    cudaFuncSetAttribute(gemm_wmma, cudaFuncAttributeMaxDynamicSharedMemorySize, GEMM_SMEM);

    // q_a = x @ wq_a^T ; rmsnorm ; q = q_a @ wq_b^T
    launch_gemm(x, wq_a, qa, NTOK, QLR, QLR, HIDDIM);
    rmsnorm_k<<<NTOK, 256>>>(qa, w_qa_ln, qa, QLR);
    launch_gemm(qa, wq_b, q, NTOK, QDIM, QDIM, QLR);

    // kv = x @ wkv_a^T (padded to 640 cols) ; split norm + k_pe rope
    launch_gemm(x, wkv_a, kv, NTOK, KVPAD, KVDIM, HIDDIM);
    kv_norm_rope_k<<<NTOK, 256>>>(w_kva_ln, rsin, rcos);

    // k_nope = ckv @ wk_b^T ; v = ckv @ wv_b^T
    launch_gemm(ckv, wk_b, knope, NTOK, KNOPE_DIM, KNOPE_DIM, KVLR);
    launch_gemm(ckv, wv_b, v, NTOK, VVDIM, VVDIM, KVLR);

    // rope on q_pe
    q_rope_k<<<(NTOK * HEADS * 32 + 255) / 256, 256>>>(rsin, rcos);

    // attention
    size_t shm = (size_t)(2 * 64 * QKSTR + 64 * VDIM + 64 * PSTR + 192) * sizeof(float);
    cudaFuncSetAttribute(attn_k, cudaFuncAttributeMaxDynamicSharedMemorySize, (int)shm);
    attn_k<<<dim3(SEQ / 64, HEADS, BATCH), AT_THREADS, shm>>>();

    // out = ao @ wo^T
    launch_gemm(ao, wo, out, NTOK, HIDDIM, HIDDIM, VVDIM);
}

// round 8
// speedup vs baseline: 1.7138x; 1.2054x over previous
#include <cuda_runtime.h>
#include <cuda_bf16.h>
#include <mma.h>
#include <math.h>
#include <stdint.h>

using namespace nvcuda;

// ---------------- problem constants ----------------
#define NTOK   4096            // B*S
#define HIDDIM 2048
#define QLR    1536
#define KVLR   512
#define HEADS  16
#define NOPE   128
#define ROPED  64
#define HD     192             // NOPE+ROPE
#define VDIM   128
#define SEQ    1024
#define BATCH  4
#define QDIM   (HEADS*HD)      // 3072
#define KVDIM  (KVLR+ROPED)    // 576
#define KVPAD  640             // padded kv width (multiple of 128)
#define KNOPE_DIM (HEADS*NOPE) // 2048
#define VVDIM  (HEADS*VDIM)    // 2048

// ---------------- fp32 scratch ----------------
__device__ float g_qa   [(size_t)NTOK*QLR];
__device__ float g_q    [(size_t)NTOK*QDIM];
__device__ float g_kv   [(size_t)NTOK*KVPAD];
__device__ float g_kpe  [(size_t)NTOK*ROPED];
__device__ float g_knope[(size_t)NTOK*KNOPE_DIM];
__device__ float g_v    [(size_t)NTOK*VVDIM];
__device__ float g_ao   [(size_t)NTOK*VVDIM];

// ---------------- bf16 hi/lo scratch ----------------
__device__ __align__(16) __nv_bfloat16 g_x_hi  [(size_t)NTOK*HIDDIM];
__device__ __align__(16) __nv_bfloat16 g_x_lo  [(size_t)NTOK*HIDDIM];
__device__ __align__(16) __nv_bfloat16 g_qn_hi [(size_t)NTOK*QLR];
__device__ __align__(16) __nv_bfloat16 g_qn_lo [(size_t)NTOK*QLR];
__device__ __align__(16) __nv_bfloat16 g_ckv_hi[(size_t)NTOK*KVLR];
__device__ __align__(16) __nv_bfloat16 g_ckv_lo[(size_t)NTOK*KVLR];
__device__ __align__(16) __nv_bfloat16 g_ao_hi [(size_t)NTOK*VVDIM];
__device__ __align__(16) __nv_bfloat16 g_ao_lo [(size_t)NTOK*VVDIM];
__device__ __align__(16) __nv_bfloat16 g_wqa_hi [(size_t)QLR*HIDDIM];
__device__ __align__(16) __nv_bfloat16 g_wqa_lo [(size_t)QLR*HIDDIM];
__device__ __align__(16) __nv_bfloat16 g_wqb_hi [(size_t)QDIM*QLR];
__device__ __align__(16) __nv_bfloat16 g_wqb_lo [(size_t)QDIM*QLR];
__device__ __align__(16) __nv_bfloat16 g_wkva_hi[(size_t)KVDIM*HIDDIM];
__device__ __align__(16) __nv_bfloat16 g_wkva_lo[(size_t)KVDIM*HIDDIM];
__device__ __align__(16) __nv_bfloat16 g_wkb_hi [(size_t)KNOPE_DIM*KVLR];
__device__ __align__(16) __nv_bfloat16 g_wkb_lo [(size_t)KNOPE_DIM*KVLR];
__device__ __align__(16) __nv_bfloat16 g_wvb_hi [(size_t)VVDIM*KVLR];
__device__ __align__(16) __nv_bfloat16 g_wvb_lo [(size_t)VVDIM*KVLR];
__device__ __align__(16) __nv_bfloat16 g_wo_hi  [(size_t)HIDDIM*VVDIM];
__device__ __align__(16) __nv_bfloat16 g_wo_lo  [(size_t)HIDDIM*VVDIM];

// ---------------- helpers ----------------
__device__ __forceinline__ uint32_t smem_u32(const void* p) {
    uint32_t a;
    asm("{ .reg .u64 t; cvta.to.shared.u64 t, %1; cvt.u32.u64 %0, t; }" : "=r"(a) : "l"(p));
    return a;
}
#define CP16(dst, src) \
    asm volatile("cp.async.cg.shared.global [%0], [%1], 16;" :: "r"(dst), "l"(src))
#define CP_COMMIT() asm volatile("cp.async.commit_group;" ::: "memory")
#define CP_WAIT(n)  asm volatile("cp.async.wait_group %0;" :: "n"(n) : "memory")

__device__ __forceinline__ float block_sum256(float v) {
    __shared__ float red[8];
    int lane = threadIdx.x & 31, w = threadIdx.x >> 5;
    #pragma unroll
    for (int o = 16; o; o >>= 1) v += __shfl_xor_sync(0xffffffffu, v, o);
    if (lane == 0) red[w] = v;
    __syncthreads();
    if (threadIdx.x == 0) {
        float t = 0.f;
        #pragma unroll
        for (int i = 0; i < 8; i++) t += red[i];
        red[0] = t;
    }
    __syncthreads();
    return red[0];
}

// ================= WMMA split-bf16 GEMM, cp.async double-buffered =================
// C[M,Nalloc] = (Ahi+Alo)[M,K] @ (Bhi+Blo)[Nvalid,K]^T (3-term, lo*lo dropped).
// CTA 128x128, BK=64, 8 warps (2m x 4n). cp.async -> smem, zero staging regs.
#define GBM 128
#define GBN 128
#define GBK 64
#define SPAD 80                       // bf16 elems; 160B rows -> 32B-aligned fragments
#define TILE_E (128*SPAD)             // 10240 elems per tile
#define STAGE_E (4*TILE_E)
#define GEMM_SMEM (2*STAGE_E*2)       // 163840 bytes

__global__ __launch_bounds__(256) void gemm_wmma(
    const __nv_bfloat16* __restrict__ Ahi, const __nv_bfloat16* __restrict__ Alo,
    const __nv_bfloat16* __restrict__ Bhi, const __nv_bfloat16* __restrict__ Blo,
    float* __restrict__ C, int M, int Nalloc, int Nvalid, int K)
{
    extern __shared__ __align__(32) char gsm[];
    __nv_bfloat16* smb = (__nv_bfloat16*)gsm;
    const uint32_t sb = smem_u32(smb);

    const int tid = threadIdx.x, wid = tid >> 5;
    const int warp_m = wid >> 2;      // 0..1
    const int warp_n = wid & 3;       // 0..3
    const int bm = blockIdx.y * GBM, bn = blockIdx.x * GBN;
    const int nch = K / GBK;

    const int sr = tid >> 3;          // rows sr, +32, +64, +96
    const int sc = tid & 7;           // 16B chunk (8 bf16)

    auto load_stage = [&](int s, int c) {
        const int k0 = c * GBK;
        const uint32_t base = sb + (uint32_t)s * (STAGE_E * 2);
        #pragma unroll
        for (int it = 0; it < 4; it++) {
            int r = sr + it * 32;
            uint32_t d = base + (uint32_t)(r * SPAD + sc * 8) * 2;
            size_t srcA = (size_t)(bm + r) * K + k0 + sc * 8;
            CP16(d + 0 * TILE_E * 2, Ahi + srcA);
            CP16(d + 1 * TILE_E * 2, Alo + srcA);
            int gn = bn + r; if (gn >= Nvalid) gn = Nvalid - 1;  // clamp; pad cols never read
            size_t srcB = (size_t)gn * K + k0 + sc * 8;
            CP16(d + 2 * TILE_E * 2, Bhi + srcB);
            CP16(d + 3 * TILE_E * 2, Blo + srcB);
        }
        CP_COMMIT();
    };

    wmma::fragment<wmma::accumulator, 16, 16, 16, float> facc[4][2];
    #pragma unroll
    for (int mi = 0; mi < 4; mi++)
        #pragma unroll
        for (int ni = 0; ni < 2; ni++) wmma::fill_fragment(facc[mi][ni], 0.0f);

    load_stage(0, 0);

    for (int c = 0; c < nch; c++) {
        if (c + 1 < nch) {
            load_stage((c + 1) & 1, c + 1);   // overlap: next stage in flight during compute
            CP_WAIT(1);                        // stage c complete
        } else {
            CP_WAIT(0);
        }
        __syncthreads();

        const int s = c & 1;
        __nv_bfloat16* sAhi = smb + s * STAGE_E;
        __nv_bfloat16* sAlo = sAhi + TILE_E;
        __nv_bfloat16* sBhi = sAhi + 2 * TILE_E;
        __nv_bfloat16* sBlo = sAhi + 3 * TILE_E;

        #pragma unroll
        for (int kk = 0; kk < GBK; kk += 16) {
            wmma::fragment<wmma::matrix_a, 16, 16, 16, __nv_bfloat16, wmma::row_major> fah[4], fal[4];
            #pragma unroll
            for (int mi = 0; mi < 4; mi++) {
                int row = warp_m * 64 + mi * 16;
                wmma::load_matrix_sync(fah[mi], sAhi + row * SPAD + kk, SPAD);
                wmma::load_matrix_sync(fal[mi], sAlo + row * SPAD + kk, SPAD);
            }
            #pragma unroll
            for (int ni = 0; ni < 2; ni++) {
                int col = warp_n * 32 + ni * 16;
                wmma::fragment<wmma::matrix_b, 16, 16, 16, __nv_bfloat16, wmma::col_major> fbh, fbl;
                wmma::load_matrix_sync(fbh, sBhi + col * SPAD + kk, SPAD);
                wmma::load_matrix_sync(fbl, sBlo + col * SPAD + kk, SPAD);
                #pragma unroll
                for (int mi = 0; mi < 4; mi++) {
                    wmma::mma_sync(facc[mi][ni], fah[mi], fbh, facc[mi][ni]);
                    wmma::mma_sync(facc[mi][ni], fah[mi], fbl, facc[mi][ni]);
                    wmma::mma_sync(facc[mi][ni], fal[mi], fbh, facc[mi][ni]);
                }
            }
        }
        __syncthreads();   // all reads of stage s done before iter c+1 overwrites it
    }

    #pragma unroll
    for (int mi = 0; mi < 4; mi++) {
        int row = bm + warp_m * 64 + mi * 16;
        #pragma unroll
        for (int ni = 0; ni < 2; ni++) {
            int col = bn + warp_n * 32 + ni * 16;
            wmma::store_matrix_sync(C + (size_t)row * Nalloc + col, facc[mi][ni],
                                    Nalloc, wmma::mem_row_major);
        }
    }
}

// ================= split / norm / rope kernels =================
__global__ void split_bf16_k(const float* __restrict__ s,
                             __nv_bfloat16* __restrict__ hi,
                             __nv_bfloat16* __restrict__ lo, int n)
{
    int i = (blockIdx.x * blockDim.x + threadIdx.x) * 8;
    if (i >= n) return;
    float4 v0 = *(const float4*)(s + i);
    float4 v1 = *(const float4*)(s + i + 4);
    float vv[8] = {v0.x, v0.y, v0.z, v0.w, v1.x, v1.y, v1.z, v1.w};
    __align__(16) __nv_bfloat16 h[8], l[8];
    #pragma unroll
    for (int e = 0; e < 8; e++) {
        h[e] = __float2bfloat16(vv[e]);
        l[e] = __float2bfloat16(vv[e] - __bfloat162float(h[e]));
    }
    *(uint4*)(hi + i) = *(uint4*)h;
    *(uint4*)(lo + i) = *(uint4*)l;
}

__global__ void rmsnorm_split_k(const float* __restrict__ in, const float* __restrict__ w,
                                __nv_bfloat16* __restrict__ hi, __nv_bfloat16* __restrict__ lo,
                                int len)
{
    int row = blockIdx.x;
    const float* h = in + (size_t)row * len;
    float ss = 0.f;
    for (int i = threadIdx.x; i < len; i += blockDim.x) { float v = h[i]; ss += v * v; }
    ss = block_sum256(ss);
    float sc = rsqrtf(ss / (float)len + 1e-6f);
    for (int i = threadIdx.x; i < len; i += blockDim.x) {
        float v = h[i] * sc * w[i];
        __nv_bfloat16 hh = __float2bfloat16(v);
        hi[(size_t)row * len + i] = hh;
        lo[(size_t)row * len + i] = __float2bfloat16(v - __bfloat162float(hh));
    }
}

__global__ void kv_norm_rope_k(const float* __restrict__ w,
                               const float* __restrict__ sin_t,
                               const float* __restrict__ cos_t)
{
    int row = blockIdx.x;
    const float* h = g_kv + (size_t)row * KVPAD;
    float ss = 0.f;
    for (int i = threadIdx.x; i < KVLR; i += blockDim.x) { float v = h[i]; ss += v * v; }
    ss = block_sum256(ss);
    float sc = rsqrtf(ss / (float)KVLR + 1e-6f);
    for (int i = threadIdx.x; i < KVLR; i += blockDim.x) {
        float v = h[i] * sc * w[i];
        __nv_bfloat16 hh = __float2bfloat16(v);
        g_ckv_hi[(size_t)row * KVLR + i] = hh;
        g_ckv_lo[(size_t)row * KVLR + i] = __float2bfloat16(v - __bfloat162float(hh));
    }
    if (threadIdx.x < ROPED / 2) {
        int i = threadIdx.x;
        int pos = row & (SEQ - 1);
        float s = sin_t[pos * 32 + i], c = cos_t[pos * 32 + i];
        float e = h[KVLR + 2 * i], o = h[KVLR + 2 * i + 1];
        g_kpe[(size_t)row * ROPED + 2 * i]     = e * c - o * s;
        g_kpe[(size_t)row * ROPED + 2 * i + 1] = e * s + o * c;
    }
}

__global__ void q_rope_k(const float* __restrict__ sin_t, const float* __restrict__ cos_t)
{
    int idx = blockIdx.x * blockDim.x + threadIdx.x;
    if (idx >= NTOK * HEADS * (ROPED / 2)) return;
    int i   = idx & 31;
    int hh  = (idx >> 5) & 15;
    int row = idx >> 9;
    int pos = row & (SEQ - 1);
    float* p = g_q + (size_t)row * QDIM + hh * HD + NOPE + 2 * i;
    float s = sin_t[pos * 32 + i], c = cos_t[pos * 32 + i];
    float e = p[0], o = p[1];
    p[0] = e * c - o * s;
    p[1] = e * s + o * c;
}

// ================= flash attention (causal, fp32) =================
#define AT_THREADS 256
#define QKSTR 196
#define PSTR  65

__global__ __launch_bounds__(AT_THREADS) void attn_k()
{
    extern __shared__ float smf[];
    float* Qs   = smf;
    float* Ks   = Qs + 64 * QKSTR;
    float* Vs   = Ks + 64 * QKSTR;
    float* Ps   = Vs + 64 * VDIM;
    float* mrow = Ps + 64 * PSTR;
    float* lrow = mrow + 64;
    float* arow = lrow + 64;

    const int qt = blockIdx.x, hh = blockIdx.y, b = blockIdx.z;
    const int tid = threadIdx.x;
    const int q0 = qt * 64;
    const int grow0 = b * SEQ + q0;

    for (int t = tid; t < 64 * 48; t += AT_THREADS) {
        int r = t / 48, c = t % 48;
        float4 v = *(const float4*)(g_q + (size_t)(grow0 + r) * QDIM + hh * HD + c * 4);
        *(float4*)&Qs[r * QKSTR + c * 4] = v;
    }
    if (tid < 64) { mrow[tid] = -INFINITY; lrow[tid] = 0.f; }

    float4 O4[8];
    #pragma unroll
    for (int k = 0; k < 8; k++) O4[k] = make_float4(0.f, 0.f, 0.f, 0.f);

    const int tx = tid & 15, ty = tid >> 4;
    const int pr = tid >> 2;
    const int cb = (tid & 3) * 4;

    __syncthreads();

    const float scale = 0.07216878364870323f;

    for (int kt = 0; kt <= qt; kt++) {
        const int k0 = kt * 64;
        const int gk0 = b * SEQ + k0;

        for (int t = tid; t < 64 * 48; t += AT_THREADS) {
            int r = t / 48, c = t % 48;
            float4 v;
            if (c < 32)
                v = *(const float4*)(g_knope + (size_t)(gk0 + r) * KNOPE_DIM + hh * NOPE + c * 4);
            else
                v = *(const float4*)(g_kpe + (size_t)(gk0 + r) * ROPED + (c - 32) * 4);
            *(float4*)&Ks[r * QKSTR + c * 4] = v;
        }
        for (int t = tid; t < 64 * 32; t += AT_THREADS) {
            int r = t / 32, c = t % 32;
            *(float4*)&Vs[r * VDIM + c * 4] =
                *(const float4*)(g_v + (size_t)(gk0 + r) * VVDIM + hh * VDIM + c * 4);
        }
        __syncthreads();

        float sacc[4][4] = {};
        #pragma unroll 4
        for (int d = 0; d < HD; d += 4) {
            float4 qv[4], kv4[4];
            #pragma unroll
            for (int ii = 0; ii < 4; ii++) qv[ii]  = *(float4*)&Qs[(ty * 4 + ii) * QKSTR + d];
            #pragma unroll
            for (int jj = 0; jj < 4; jj++) kv4[jj] = *(float4*)&Ks[(tx + 16 * jj) * QKSTR + d];
            #pragma unroll
            for (int ii = 0; ii < 4; ii++)
                #pragma unroll
                for (int jj = 0; jj < 4; jj++)
                    sacc[ii][jj] += qv[ii].x * kv4[jj].x + qv[ii].y * kv4[jj].y
                                  + qv[ii].z * kv4[jj].z + qv[ii].w * kv4[jj].w;
        }
        #pragma unroll
        for (int ii = 0; ii < 4; ii++)
            #pragma unroll
            for (int jj = 0; jj < 4; jj++) {
                int qi = q0 + ty * 4 + ii;
                int kj = k0 + tx + 16 * jj;
                Ps[(ty * 4 + ii) * PSTR + tx + 16 * jj] =
                    (kj <= qi) ? sacc[ii][jj] * scale : -1e30f;
            }
        __syncthreads();

        {
            int lane = tid & 31;
            int rbase = (tid >> 5) * 8;
            #pragma unroll
            for (int rr = 0; rr < 8; rr++) {
                int r = rbase + rr;
                float v0 = Ps[r * PSTR + lane];
                float v1 = Ps[r * PSTR + 32 + lane];
                float mx = fmaxf(v0, v1);
                #pragma unroll
                for (int o = 16; o; o >>= 1) mx = fmaxf(mx, __shfl_xor_sync(0xffffffffu, mx, o));
                float mold = mrow[r];
                float mnew = fmaxf(mold, mx);
                float p0 = __expf(v0 - mnew), p1 = __expf(v1 - mnew);
                Ps[r * PSTR + lane] = p0;
                Ps[r * PSTR + 32 + lane] = p1;
                float s = p0 + p1;
                #pragma unroll
                for (int o = 16; o; o >>= 1) s += __shfl_xor_sync(0xffffffffu, s, o);
                if (lane == 0) {
                    float a = (mold > -1e30f) ? __expf(mold - mnew) : 0.f;
                    arow[r] = a;
                    lrow[r] = lrow[r] * a + s;
                    mrow[r] = mnew;
                }
            }
        }
        __syncthreads();

        {
            float a = arow[pr];
            #pragma unroll
            for (int k = 0; k < 8; k++) {
                O4[k].x *= a; O4[k].y *= a; O4[k].z *= a; O4[k].w *= a;
            }
            #pragma unroll 2
            for (int j = 0; j < 64; j++) {
                float p = Ps[pr * PSTR + j];
                #pragma unroll
                for (int k = 0; k < 8; k++) {
                    float4 v = *(float4*)&Vs[j * VDIM + cb + 16 * k];
                    O4[k].x = fmaf(p, v.x, O4[k].x);
                    O4[k].y = fmaf(p, v.y, O4[k].y);
                    O4[k].z = fmaf(p, v.z, O4[k].z);
                    O4[k].w = fmaf(p, v.w, O4[k].w);
                }
            }
        }
        __syncthreads();
    }

    float inv = 1.f / lrow[pr];
    #pragma unroll
    for (int k = 0; k < 8; k++) {
        float4 v = make_float4(O4[k].x * inv, O4[k].y * inv, O4[k].z * inv, O4[k].w * inv);
        *(float4*)(g_ao + (size_t)(grow0 + pr) * VVDIM + hh * VDIM + cb + 16 * k) = v;
    }
}

// ================= host launch =================
static inline void launch_split(const float* s, __nv_bfloat16* hi, __nv_bfloat16* lo, size_t n) {
    split_bf16_k<<<(unsigned)((n / 8 + 255) / 256), 256>>>(s, hi, lo, (int)n);
}
static inline void launch_gemm(const __nv_bfloat16* ah, const __nv_bfloat16* al,
                               const __nv_bfloat16* bh, const __nv_bfloat16* bl,
                               float* c, int M, int Nalloc, int Nvalid, int K)
{
    dim3 grid(Nalloc / GBN, M / GBM);
    gemm_wmma<<<grid, 256, GEMM_SMEM>>>(ah, al, bh, bl, c, M, Nalloc, Nvalid, K);
}

extern "C" void kernel_launch(void* const* d_in, const int* in_sizes, int n_in,
                              void* d_out, int out_size)
{
    const float* x        = (const float*)d_in[0];
    const float* wq_a     = (const float*)d_in[1];
    const float* w_qa_ln  = (const float*)d_in[2];
    const float* wq_b     = (const float*)d_in[3];
    const float* wkv_a    = (const float*)d_in[4];
    const float* w_kva_ln = (const float*)d_in[5];
    const float* wk_b     = (const float*)d_in[6];
    const float* wv_b     = (const float*)d_in[7];
    const float* wo       = (const float*)d_in[8];
    const float* rsin     = (const float*)d_in[9];
    const float* rcos     = (const float*)d_in[10];
    float* out = (float*)d_out;

    float *qa, *q, *kv, *knope, *v, *ao;
    cudaGetSymbolAddress((void**)&qa,    g_qa);
    cudaGetSymbolAddress((void**)&q,     g_q);
    cudaGetSymbolAddress((void**)&kv,    g_kv);
    cudaGetSymbolAddress((void**)&knope, g_knope);
    cudaGetSymbolAddress((void**)&v,     g_v);
    cudaGetSymbolAddress((void**)&ao,    g_ao);

    __nv_bfloat16 *xh, *xl, *qnh, *qnl, *ckvh, *ckvl, *aoh, *aol;
    __nv_bfloat16 *wqah, *wqal, *wqbh, *wqbl, *wkvah, *wkval, *wkbh, *wkbl, *wvbh, *wvbl, *woh, *wol;
    cudaGetSymbolAddress((void**)&xh,   g_x_hi);   cudaGetSymbolAddress((void**)&xl,   g_x_lo);
    cudaGetSymbolAddress((void**)&qnh,  g_qn_hi);  cudaGetSymbolAddress((void**)&qnl,  g_qn_lo);
    cudaGetSymbolAddress((void**)&ckvh, g_ckv_hi); cudaGetSymbolAddress((void**)&ckvl, g_ckv_lo);
    cudaGetSymbolAddress((void**)&aoh,  g_ao_hi);  cudaGetSymbolAddress((void**)&aol,  g_ao_lo);
    cudaGetSymbolAddress((void**)&wqah, g_wqa_hi); cudaGetSymbolAddress((void**)&wqal, g_wqa_lo);
    cudaGetSymbolAddress((void**)&wqbh, g_wqb_hi); cudaGetSymbolAddress((void**)&wqbl, g_wqb_lo);
    cudaGetSymbolAddress((void**)&wkvah,g_wkva_hi);cudaGetSymbolAddress((void**)&wkval,g_wkva_lo);
    cudaGetSymbolAddress((void**)&wkbh, g_wkb_hi); cudaGetSymbolAddress((void**)&wkbl, g_wkb_lo);
    cudaGetSymbolAddress((void**)&wvbh, g_wvb_hi); cudaGetSymbolAddress((void**)&wvbl, g_wvb_lo);
    cudaGetSymbolAddress((void**)&woh,  g_wo_hi);  cudaGetSymbolAddress((void**)&wol,  g_wo_lo);

    cudaFuncSetAttribute(gemm_wmma, cudaFuncAttributeMaxDynamicSharedMemorySize, GEMM_SMEM);

    // one-time-per-call splits (bandwidth-bound, ~80us total)
    launch_split(x,     xh,   xl,   (size_t)NTOK * HIDDIM);
    launch_split(wq_a,  wqah, wqal, (size_t)QLR * HIDDIM);
    launch_split(wq_b,  wqbh, wqbl, (size_t)QDIM * QLR);
    launch_split(wkv_a, wkvah,wkval,(size_t)KVDIM * HIDDIM);
    launch_split(wk_b,  wkbh, wkbl, (size_t)KNOPE_DIM * KVLR);
    launch_split(wv_b,  wvbh, wvbl, (size_t)VVDIM * KVLR);
    launch_split(wo,    woh,  wol,  (size_t)HIDDIM * VVDIM);

    // q_a = x @ wq_a^T ; rmsnorm+split ; q = qn @ wq_b^T
    launch_gemm(xh, xl, wqah, wqal, qa, NTOK, QLR, QLR, HIDDIM);
    rmsnorm_split_k<<<NTOK, 256>>>(qa, w_qa_ln, qnh, qnl, QLR);
    launch_gemm(qnh, qnl, wqbh, wqbl, q, NTOK, QDIM, QDIM, QLR);

    // kv = x @ wkv_a^T (padded to 640) ; norm+rope+split
    launch_gemm(xh, xl, wkvah, wkval, kv, NTOK, KVPAD, KVDIM, HIDDIM);
    kv_norm_rope_k<<<NTOK, 256>>>(w_kva_ln, rsin, rcos);

    // k_nope / v
    launch_gemm(ckvh, ckvl, wkbh, wkbl, knope, NTOK, KNOPE_DIM, KNOPE_DIM, KVLR);
    launch_gemm(ckvh, ckvl, wvbh, wvbl, v, NTOK, VVDIM, VVDIM, KVLR);

    // rope on q_pe
    q_rope_k<<<(NTOK * HEADS * 32 + 255) / 256, 256>>>(rsin, rcos);

    // attention
    size_t shm = (size_t)(2 * 64 * QKSTR + 64 * VDIM + 64 * PSTR + 192) * sizeof(float);
    cudaFuncSetAttribute(attn_k, cudaFuncAttributeMaxDynamicSharedMemorySize, (int)shm);
    attn_k<<<dim3(SEQ / 64, HEADS, BATCH), AT_THREADS, shm>>>();

    // out = ao @ wo^T
    launch_split(ao, aoh, aol, (size_t)NTOK * VVDIM);
    launch_gemm(aoh, aol, woh, wol, out, NTOK, HIDDIM, HIDDIM, VVDIM);
}